// round 16
// baseline (speedup 1.0000x reference)
#include <cuda_runtime.h>
#include <cuda_fp16.h>
#include <math.h>
#include <stdint.h>

#define DIM 4096
#define NHEADS 32
#define NKV 8
#define HD 128
#define SEQ 2048
#define BSZ 2
#define TOK (BSZ*SEQ)
#define KVDIM (NKV*HD)
#define NQKV (DIM + 2*KVDIM)   // 6144

// fp16 scratch (no cudaMalloc allowed)
__device__ __half g_xh[(size_t)TOK * DIM];
__device__ __half g_wqkvh[(size_t)NQKV * DIM];
__device__ __half g_woh[(size_t)DIM * DIM];
__device__ __half g_qh[(size_t)TOK * DIM];
__device__ __half g_kh[(size_t)TOK * KVDIM];
__device__ __half g_vh[(size_t)TOK * KVDIM];
__device__ __half g_ah[(size_t)TOK * DIM];

// ---------------------------------------------------------------------------
// PTX helpers
// ---------------------------------------------------------------------------
__device__ __forceinline__ uint32_t smem_u32(const void* p) {
    return (uint32_t)__cvta_generic_to_shared(p);
}
__device__ __forceinline__ void cp16(uint32_t dst, const void* src) {
    asm volatile("cp.async.cg.shared.global [%0], [%1], 16;\n" ::"r"(dst), "l"(src));
}
#define CP_COMMIT asm volatile("cp.async.commit_group;\n" ::: "memory")
#define CP_WAIT0  asm volatile("cp.async.wait_group 0;\n" ::: "memory")
#define CP_WAIT1  asm volatile("cp.async.wait_group 1;\n" ::: "memory")

__device__ __forceinline__ void ldsm4(uint32_t& r0, uint32_t& r1, uint32_t& r2,
                                      uint32_t& r3, uint32_t addr) {
    asm volatile("ldmatrix.sync.aligned.m8n8.x4.shared.b16 {%0,%1,%2,%3}, [%4];\n"
                 : "=r"(r0), "=r"(r1), "=r"(r2), "=r"(r3) : "r"(addr));
}
__device__ __forceinline__ void ldsm4t(uint32_t& r0, uint32_t& r1, uint32_t& r2,
                                       uint32_t& r3, uint32_t addr) {
    asm volatile("ldmatrix.sync.aligned.m8n8.x4.trans.shared.b16 {%0,%1,%2,%3}, [%4];\n"
                 : "=r"(r0), "=r"(r1), "=r"(r2), "=r"(r3) : "r"(addr));
}
__device__ __forceinline__ void mma_f16(float* c, const uint32_t* a,
                                        uint32_t b0, uint32_t b1) {
    asm volatile(
        "mma.sync.aligned.m16n8k16.row.col.f32.f16.f16.f32 "
        "{%0,%1,%2,%3}, {%4,%5,%6,%7}, {%8,%9}, {%0,%1,%2,%3};\n"
        : "+f"(c[0]), "+f"(c[1]), "+f"(c[2]), "+f"(c[3])
        : "r"(a[0]), "r"(a[1]), "r"(a[2]), "r"(a[3]), "r"(b0), "r"(b1));
}
__device__ __forceinline__ uint32_t pack_h2(float x, float y) {
    __half2 h = __floats2half2_rn(x, y);
    return *(uint32_t*)&h;
}
__device__ __forceinline__ float fex2(float x) {
    float y;
    asm("ex2.approx.ftz.f32 %0, %1;" : "=f"(y) : "f"(x));
    return y;
}

// ---------------------------------------------------------------------------
// Single merged fp32 -> fp16 conversion for x, wq, wk, wv, wo (8 elems/thr)
// ---------------------------------------------------------------------------
#define SEG0 ((size_t)TOK * DIM)
#define SEG1 ((size_t)DIM * DIM)
#define SEG2 ((size_t)KVDIM * DIM)
#define SEG3 ((size_t)KVDIM * DIM)
#define SEG4 ((size_t)DIM * DIM)
#define CVT_TOTAL (SEG0 + SEG1 + SEG2 + SEG3 + SEG4)

__global__ void cvt_all(const float* __restrict__ x, const float* __restrict__ wq,
                        const float* __restrict__ wk, const float* __restrict__ wv,
                        const float* __restrict__ wo, __half* __restrict__ xh,
                        __half* __restrict__ wqkvh, __half* __restrict__ woh) {
    size_t i = (size_t)(blockIdx.x * blockDim.x + threadIdx.x) * 8;
    if (i >= CVT_TOTAL) return;
    const float* src;
    __half* dst;
    size_t off;
    if (i < SEG0) { src = x; dst = xh; off = i; }
    else if (i < SEG0 + SEG1) { src = wq; dst = wqkvh; off = i - SEG0; }
    else if (i < SEG0 + SEG1 + SEG2) {
        src = wk; dst = wqkvh + SEG1; off = i - SEG0 - SEG1;
    } else if (i < SEG0 + SEG1 + SEG2 + SEG3) {
        src = wv; dst = wqkvh + SEG1 + SEG2; off = i - SEG0 - SEG1 - SEG2;
    } else { src = wo; dst = woh; off = i - SEG0 - SEG1 - SEG2 - SEG3; }

    float4 v0 = *(const float4*)(src + off);
    float4 v1 = *(const float4*)(src + off + 4);
    __half2 h0 = __floats2half2_rn(v0.x, v0.y);
    __half2 h1 = __floats2half2_rn(v0.z, v0.w);
    __half2 h2 = __floats2half2_rn(v1.x, v1.y);
    __half2 h3 = __floats2half2_rn(v1.z, v1.w);
    uint4 o;
    o.x = *(uint32_t*)&h0; o.y = *(uint32_t*)&h1;
    o.z = *(uint32_t*)&h2; o.w = *(uint32_t*)&h3;
    *(uint4*)(dst + off) = o;
}

// ---------------------------------------------------------------------------
// fp16 GEMM: C[M,N] = A[M,K] @ B[N,K]^T + bias
// CTA tile 128x128x64, 128 threads (4 warps, 2x2), warp tile 64x64,
// 3-stage cp.async pipeline (wait_group 1 at loop head keeps one load
// group in flight -> no per-iteration drain), stride-72 padded smem,
// 110.6KB -> 2 CTAs/SM.
// MODE 0: fp32 out. MODE 1: fused QKV -> split fp16 + RoPE, bias bq/bk/bv.
// ---------------------------------------------------------------------------
#define BK 64
#define GSTR 72
#define A_STG (128 * GSTR)
#define B_STG (128 * GSTR)
#define GEMM_SMEM (3 * (A_STG + B_STG) * 2)   // 110592 bytes

template <int MODE>
__global__ __launch_bounds__(128, 2)
void h_gemm3(const __half* __restrict__ A, const __half* __restrict__ B,
             const float* __restrict__ bias_q, const float* __restrict__ bias_k,
             const float* __restrict__ bias_v, float* __restrict__ Cf,
             __half* __restrict__ Cq, __half* __restrict__ Ck,
             __half* __restrict__ Cv, const float* __restrict__ cs,
             const float* __restrict__ sn, int M, int N, int K) {
    extern __shared__ __half sh[];
    __half* As = sh;                 // [3][A_STG]
    __half* Bs = sh + 3 * A_STG;     // [3][B_STG]

    const int tid = threadIdx.x;
    const int lane = tid & 31;
    const int wid = tid >> 5;
    const int wm = wid >> 1;
    const int wn = wid & 1;
    const int bm = blockIdx.y * 128;
    const int bn = blockIdx.x * 128;
    const int lr = lane & 7;
    const int gq = lane >> 3;

    float acc[4][8][4];
#pragma unroll
    for (int mi = 0; mi < 4; mi++)
#pragma unroll
        for (int ni = 0; ni < 8; ni++)
#pragma unroll
            for (int j = 0; j < 4; j++) acc[mi][ni][j] = 0.f;

    auto g2s = [&](int k0, int stg) {
#pragma unroll
        for (int p = 0; p < 8; p++) {
            int cid = tid + 128 * p;
            int row = cid >> 3;
            int ch = cid & 7;
            cp16(smem_u32(&As[stg * A_STG + row * GSTR + ch * 8]),
                 A + (size_t)(bm + row) * K + k0 + ch * 8);
        }
#pragma unroll
        for (int p = 0; p < 8; p++) {
            int cid = tid + 128 * p;
            int row = cid >> 3;
            int ch = cid & 7;
            cp16(smem_u32(&Bs[stg * B_STG + row * GSTR + ch * 8]),
                 B + (size_t)(bn + row) * K + k0 + ch * 8);
        }
    };

    const int nit = K / BK;
    g2s(0, 0); CP_COMMIT;
    g2s(BK, 1); CP_COMMIT;

    int buf = 0;
    for (int it = 0; it < nit; it++) {
        CP_WAIT1;                 // group(it) done; group(it+1) may be in flight
        __syncthreads();
        if (it + 2 < nit) { g2s((it + 2) * BK, (it + 2) % 3); CP_COMMIT; }

#pragma unroll
        for (int kk2 = 0; kk2 < 4; kk2++) {
            int kk = kk2 * 16;
            uint32_t a[4][4];
#pragma unroll
            for (int mi = 0; mi < 4; mi++)
                ldsm4(a[mi][0], a[mi][1], a[mi][2], a[mi][3],
                      smem_u32(&As[buf * A_STG +
                                   (wm * 64 + mi * 16 + lr + (gq & 1) * 8) * GSTR +
                                   kk + (gq >> 1) * 8]));
#pragma unroll
            for (int nt = 0; nt < 4; nt++) {
                uint32_t b0, b1, b2, b3;
                ldsm4(b0, b1, b2, b3,
                      smem_u32(&Bs[buf * B_STG +
                                   (wn * 64 + nt * 16 + lr + (gq & 1) * 8) * GSTR +
                                   kk + (gq >> 1) * 8]));
#pragma unroll
                for (int mi = 0; mi < 4; mi++) {
                    mma_f16(acc[mi][nt * 2], a[mi], b0, b2);
                    mma_f16(acc[mi][nt * 2 + 1], a[mi], b1, b3);
                }
            }
        }
        buf = (buf + 1) % 3;
    }

    // ---- epilogue ----
    const int r0 = bm + wm * 64 + (lane >> 2);
    const int c0 = bn + wn * 64 + (lane & 3) * 2;
#pragma unroll
    for (int mi = 0; mi < 4; mi++) {
#pragma unroll
        for (int ni = 0; ni < 8; ni++) {
            int r = r0 + mi * 16;
            int c = c0 + ni * 8;
            float2 bb;
            if (MODE == 0) bb = *(const float2*)&bias_q[c];
            else {
                if (c < DIM)                bb = *(const float2*)&bias_q[c];
                else if (c < DIM + KVDIM)   bb = *(const float2*)&bias_k[c - DIM];
                else                        bb = *(const float2*)&bias_v[c - DIM - KVDIM];
            }
            float v00 = acc[mi][ni][0] + bb.x, v01 = acc[mi][ni][1] + bb.y;
            float v10 = acc[mi][ni][2] + bb.x, v11 = acc[mi][ni][3] + bb.y;
            if (MODE == 0) {
                *(float2*)&Cf[(size_t)r * N + c] = make_float2(v00, v01);
                *(float2*)&Cf[(size_t)(r + 8) * N + c] = make_float2(v10, v11);
            } else {
                if (c < DIM + KVDIM) {
                    int i = (c & 127) >> 1;
                    int s0 = r & (SEQ - 1), s1 = (r + 8) & (SEQ - 1);
                    float c00 = cs[s0 * 64 + i], sn0 = sn[s0 * 64 + i];
                    float c10 = cs[s1 * 64 + i], sn1 = sn[s1 * 64 + i];
                    float a0 = v00, b0v = v01;
                    v00 = a0 * c00 - b0v * sn0;
                    v01 = a0 * sn0 + b0v * c00;
                    float a1 = v10, b1v = v11;
                    v10 = a1 * c10 - b1v * sn1;
                    v11 = a1 * sn1 + b1v * c10;
                }
                __half2 h0 = __floats2half2_rn(v00, v01);
                __half2 h1 = __floats2half2_rn(v10, v11);
                __half* dst;
                size_t str;
                int cc;
                if (c < DIM) { dst = Cq; str = DIM; cc = c; }
                else if (c < DIM + KVDIM) { dst = Ck; str = KVDIM; cc = c - DIM; }
                else { dst = Cv; str = KVDIM; cc = c - DIM - KVDIM; }
                *(__half2*)&dst[(size_t)r * str + cc] = h0;
                *(__half2*)&dst[(size_t)(r + 8) * str + cc] = h1;
            }
        }
    }
}

// ---------------------------------------------------------------------------
// Causal GQA flash attention (R10 config, measured 274us) — unchanged.
// QT=64, KT=64, 128 threads, K/V double-buffered, 87KB -> 2 CTAs/SM.
// ---------------------------------------------------------------------------
#define FSTR 136
#define QT 64
#define KT 64
#define FA_SMEM ((QT * FSTR + 2 * KT * FSTR + 2 * KT * FSTR) * 2)  // 87040

__global__ __launch_bounds__(128, 2)
void flash_h(const __half* __restrict__ Q, const __half* __restrict__ K,
             const __half* __restrict__ V, __half* __restrict__ O) {
    extern __shared__ __half sm[];
    __half* Qs = sm;
    __half* Ks = Qs + QT * FSTR;
    __half* Vs = Ks + 2 * KT * FSTR;

    const int tid = threadIdx.x;
    const int lane = tid & 31;
    const int w = tid >> 5;
    const int q0 = (gridDim.x - 1 - blockIdx.x) * QT;
    const int bh = blockIdx.y;
    const int b = bh >> 5;
    const int h = bh & 31;
    const int g = h >> 2;
    const int lr = lane & 7;
    const int gq = lane >> 3;
    const int qr = lane >> 2;
    const int qc = (lane & 3) * 2;

    const __half* Qg = Q + (size_t)(b * SEQ + q0) * DIM + h * HD;
    const __half* Kg = K + (size_t)(b * SEQ) * KVDIM + g * HD;
    const __half* Vg = V + (size_t)(b * SEQ) * KVDIM + g * HD;

#pragma unroll
    for (int p = 0; p < 8; p++) {
        int cid = tid + 128 * p;
        int row = cid >> 4, ch = cid & 15;
        cp16(smem_u32(&Qs[row * FSTR + ch * 8]), Qg + (size_t)row * DIM + ch * 8);
    }
    CP_COMMIT;

    auto ldKV = [&](int kv0, int bufl) {
#pragma unroll
        for (int p = 0; p < 8; p++) {
            int cid = tid + 128 * p;
            int row = cid >> 4, ch = cid & 15;
            cp16(smem_u32(&Ks[bufl * KT * FSTR + row * FSTR + ch * 8]),
                 Kg + (size_t)(kv0 + row) * KVDIM + ch * 8);
            cp16(smem_u32(&Vs[bufl * KT * FSTR + row * FSTR + ch * 8]),
                 Vg + (size_t)(kv0 + row) * KVDIM + ch * 8);
        }
    };
    ldKV(0, 0);
    CP_COMMIT;

    float o[16][4];
#pragma unroll
    for (int nt = 0; nt < 16; nt++)
#pragma unroll
        for (int j = 0; j < 4; j++) o[nt][j] = 0.f;
    float mA = -1e30f, mB = -1e30f, lA = 0.f, lB = 0.f;
    const float scale2 = 0.08838834764831845f * 1.4426950408889634f;
    const int niter = q0 / KT + 1;
    const int rA = q0 + w * 16 + qr;

    for (int it = 0; it < niter; it++) {
        const int kv0 = it * KT;
        const int buf = it & 1;
        CP_WAIT0;
        __syncthreads();
        if (it + 1 < niter) { ldKV((it + 1) * KT, buf ^ 1); CP_COMMIT; }

        float s[8][4];
#pragma unroll
        for (int nt = 0; nt < 8; nt++)
#pragma unroll
            for (int j = 0; j < 4; j++) s[nt][j] = 0.f;

#pragma unroll
        for (int ks = 0; ks < 8; ks++) {
            uint32_t a[4];
            ldsm4(a[0], a[1], a[2], a[3],
                  smem_u32(&Qs[(w * 16 + lr + (gq & 1) * 8) * FSTR +
                               ks * 16 + (gq >> 1) * 8]));
#pragma unroll
            for (int np = 0; np < 4; np++) {
                uint32_t b0, b1, b2, b3;
                ldsm4(b0, b1, b2, b3,
                      smem_u32(&Ks[buf * KT * FSTR +
                                   (np * 16 + lr + (gq & 1) * 8) * FSTR +
                                   ks * 16 + (gq >> 1) * 8]));
                mma_f16(s[np * 2], a, b0, b2);
                mma_f16(s[np * 2 + 1], a, b1, b3);
            }
        }

        const bool domask = (kv0 + KT - 1) > (q0 + w * 16);
#pragma unroll
        for (int nt = 0; nt < 8; nt++)
#pragma unroll
            for (int j = 0; j < 4; j++) {
                float v = s[nt][j] * scale2;
                if (domask) {
                    int col = kv0 + nt * 8 + qc + (j & 1);
                    int row = rA + (j >> 1) * 8;
                    if (col > row) v = -1e30f;
                }
                s[nt][j] = v;
            }

        float rmA = -1e30f, rmB = -1e30f;
#pragma unroll
        for (int nt = 0; nt < 8; nt++) {
            rmA = fmaxf(rmA, fmaxf(s[nt][0], s[nt][1]));
            rmB = fmaxf(rmB, fmaxf(s[nt][2], s[nt][3]));
        }
        rmA = fmaxf(rmA, __shfl_xor_sync(0xffffffffu, rmA, 1));
        rmA = fmaxf(rmA, __shfl_xor_sync(0xffffffffu, rmA, 2));
        rmB = fmaxf(rmB, __shfl_xor_sync(0xffffffffu, rmB, 1));
        rmB = fmaxf(rmB, __shfl_xor_sync(0xffffffffu, rmB, 2));

        float newmA = fmaxf(mA, rmA), newmB = fmaxf(mB, rmB);
        float aAl = fex2(mA - newmA), aBl = fex2(mB - newmB);
        float lsA = 0.f, lsB = 0.f;
#pragma unroll
        for (int nt = 0; nt < 8; nt++) {
            s[nt][0] = fex2(s[nt][0] - newmA);
            s[nt][1] = fex2(s[nt][1] - newmA);
            s[nt][2] = fex2(s[nt][2] - newmB);
            s[nt][3] = fex2(s[nt][3] - newmB);
            lsA += s[nt][0] + s[nt][1];
            lsB += s[nt][2] + s[nt][3];
        }
        lsA += __shfl_xor_sync(0xffffffffu, lsA, 1);
        lsA += __shfl_xor_sync(0xffffffffu, lsA, 2);
        lsB += __shfl_xor_sync(0xffffffffu, lsB, 1);
        lsB += __shfl_xor_sync(0xffffffffu, lsB, 2);
        lA = lA * aAl + lsA;
        lB = lB * aBl + lsB;
        mA = newmA;
        mB = newmB;
        if (!__all_sync(0xffffffffu, (aAl == 1.f) & (aBl == 1.f))) {
#pragma unroll
            for (int nt = 0; nt < 16; nt++) {
                o[nt][0] *= aAl; o[nt][1] *= aAl;
                o[nt][2] *= aBl; o[nt][3] *= aBl;
            }
        }

        uint32_t pa[4][4];
#pragma unroll
        for (int t = 0; t < 4; t++) {
            pa[t][0] = pack_h2(s[2 * t][0], s[2 * t][1]);
            pa[t][1] = pack_h2(s[2 * t][2], s[2 * t][3]);
            pa[t][2] = pack_h2(s[2 * t + 1][0], s[2 * t + 1][1]);
            pa[t][3] = pack_h2(s[2 * t + 1][2], s[2 * t + 1][3]);
        }

#pragma unroll
        for (int t = 0; t < 4; t++) {
#pragma unroll
            for (int np = 0; np < 8; np++) {
                uint32_t v0, v1, v2, v3;
                ldsm4t(v0, v1, v2, v3,
                       smem_u32(&Vs[buf * KT * FSTR +
                                    (t * 16 + lr + (gq & 1) * 8) * FSTR +
                                    np * 16 + (gq >> 1) * 8]));
                mma_f16(o[np * 2], pa[t], v0, v1);
                mma_f16(o[np * 2 + 1], pa[t], v2, v3);
            }
        }
    }

    float iA = 1.f / lA, iB = 1.f / lB;
    __half* Og = O + (size_t)(b * SEQ + q0 + w * 16) * DIM + h * HD;
#pragma unroll
    for (int nt = 0; nt < 16; nt++) {
        int c = nt * 8 + qc;
        *(__half2*)&Og[(size_t)qr * DIM + c] =
            __floats2half2_rn(o[nt][0] * iA, o[nt][1] * iA);
        *(__half2*)&Og[(size_t)(qr + 8) * DIM + c] =
            __floats2half2_rn(o[nt][2] * iB, o[nt][3] * iB);
    }
}

// ---------------------------------------------------------------------------
extern "C" void kernel_launch(void* const* d_in, const int* in_sizes, int n_in,
                              void* d_out, int out_size) {
    const float* x   = (const float*)d_in[0];
    const float* fcs = (const float*)d_in[1];
    const float* fsn = (const float*)d_in[2];
    const float* wq = (const float*)d_in[4];
    const float* bq = (const float*)d_in[5];
    const float* wk = (const float*)d_in[6];
    const float* bk = (const float*)d_in[7];
    const float* wv = (const float*)d_in[8];
    const float* bv = (const float*)d_in[9];
    const float* wo = (const float*)d_in[10];
    const float* bo = (const float*)d_in[11];
    float* out = (float*)d_out;

    __half *xh, *wqkvh, *woh, *qh, *kh, *vh, *ah;
    cudaGetSymbolAddress((void**)&xh, g_xh);
    cudaGetSymbolAddress((void**)&wqkvh, g_wqkvh);
    cudaGetSymbolAddress((void**)&woh, g_woh);
    cudaGetSymbolAddress((void**)&qh, g_qh);
    cudaGetSymbolAddress((void**)&kh, g_kh);
    cudaGetSymbolAddress((void**)&vh, g_vh);
    cudaGetSymbolAddress((void**)&ah, g_ah);

    cudaFuncSetAttribute(h_gemm3<0>, cudaFuncAttributeMaxDynamicSharedMemorySize,
                         GEMM_SMEM);
    cudaFuncSetAttribute(h_gemm3<1>, cudaFuncAttributeMaxDynamicSharedMemorySize,
                         GEMM_SMEM);
    cudaFuncSetAttribute(flash_h, cudaFuncAttributeMaxDynamicSharedMemorySize,
                         FA_SMEM);

    // All fp32->fp16 conversions in ONE launch
    cvt_all<<<(int)((CVT_TOTAL / 8 + 255) / 256), 256>>>(
        x, wq, wk, wv, wo, xh, wqkvh, woh);

    // Fused QKV projection + RoPE epilogue
    h_gemm3<1><<<dim3(NQKV / 128, TOK / 128), 128, GEMM_SMEM>>>(
        xh, wqkvh, bq, bk, bv, nullptr, qh, kh, vh, fcs, fsn, TOK, NQKV, DIM);

    // Flash attention
    flash_h<<<dim3(SEQ / QT, BSZ * NHEADS), 128, FA_SMEM>>>(qh, kh, vh, ah);

    // Output projection (fp32 out)
    h_gemm3<0><<<dim3(DIM / 128, TOK / 128), 128, GEMM_SMEM>>>(
        ah, woh, bo, nullptr, nullptr, out, nullptr, nullptr, nullptr,
        nullptr, nullptr, TOK, DIM, DIM);
}

// round 17
// speedup vs baseline: 1.0356x; 1.0356x over previous
#include <cuda_runtime.h>
#include <cuda_fp16.h>
#include <math.h>
#include <stdint.h>

#define DIM 4096
#define NHEADS 32
#define NKV 8
#define HD 128
#define SEQ 2048
#define BSZ 2
#define TOK (BSZ*SEQ)
#define KVDIM (NKV*HD)
#define NQKV (DIM + 2*KVDIM)   // 6144

// fp16 scratch (no cudaMalloc allowed)
__device__ __half g_xh[(size_t)TOK * DIM];
__device__ __half g_wqkvh[(size_t)NQKV * DIM];
__device__ __half g_woh[(size_t)DIM * DIM];
__device__ __half g_qh[(size_t)TOK * DIM];
__device__ __half g_kh[(size_t)TOK * KVDIM];
__device__ __half g_vh[(size_t)TOK * KVDIM];
__device__ __half g_ah[(size_t)TOK * DIM];

// ---------------------------------------------------------------------------
// PTX helpers
// ---------------------------------------------------------------------------
__device__ __forceinline__ uint32_t smem_u32(const void* p) {
    return (uint32_t)__cvta_generic_to_shared(p);
}
__device__ __forceinline__ void cp16(uint32_t dst, const void* src) {
    asm volatile("cp.async.cg.shared.global [%0], [%1], 16;\n" ::"r"(dst), "l"(src));
}
#define CP_COMMIT asm volatile("cp.async.commit_group;\n" ::: "memory")
#define CP_WAIT0  asm volatile("cp.async.wait_group 0;\n" ::: "memory")

__device__ __forceinline__ void ldsm4(uint32_t& r0, uint32_t& r1, uint32_t& r2,
                                      uint32_t& r3, uint32_t addr) {
    asm volatile("ldmatrix.sync.aligned.m8n8.x4.shared.b16 {%0,%1,%2,%3}, [%4];\n"
                 : "=r"(r0), "=r"(r1), "=r"(r2), "=r"(r3) : "r"(addr));
}
__device__ __forceinline__ void ldsm4t(uint32_t& r0, uint32_t& r1, uint32_t& r2,
                                       uint32_t& r3, uint32_t addr) {
    asm volatile("ldmatrix.sync.aligned.m8n8.x4.trans.shared.b16 {%0,%1,%2,%3}, [%4];\n"
                 : "=r"(r0), "=r"(r1), "=r"(r2), "=r"(r3) : "r"(addr));
}
__device__ __forceinline__ void mma_f16(float* c, const uint32_t* a,
                                        uint32_t b0, uint32_t b1) {
    asm volatile(
        "mma.sync.aligned.m16n8k16.row.col.f32.f16.f16.f32 "
        "{%0,%1,%2,%3}, {%4,%5,%6,%7}, {%8,%9}, {%0,%1,%2,%3};\n"
        : "+f"(c[0]), "+f"(c[1]), "+f"(c[2]), "+f"(c[3])
        : "r"(a[0]), "r"(a[1]), "r"(a[2]), "r"(a[3]), "r"(b0), "r"(b1));
}
__device__ __forceinline__ uint32_t pack_h2(float x, float y) {
    __half2 h = __floats2half2_rn(x, y);
    return *(uint32_t*)&h;
}
__device__ __forceinline__ float fex2(float x) {
    float y;
    asm("ex2.approx.ftz.f32 %0, %1;" : "=f"(y) : "f"(x));
    return y;
}

// ---------------------------------------------------------------------------
// Single merged fp32 -> fp16 conversion for x, wq, wk, wv, wo (8 elems/thr)
// ---------------------------------------------------------------------------
#define SEG0 ((size_t)TOK * DIM)
#define SEG1 ((size_t)DIM * DIM)
#define SEG2 ((size_t)KVDIM * DIM)
#define SEG3 ((size_t)KVDIM * DIM)
#define SEG4 ((size_t)DIM * DIM)
#define CVT_TOTAL (SEG0 + SEG1 + SEG2 + SEG3 + SEG4)

__global__ void cvt_all(const float* __restrict__ x, const float* __restrict__ wq,
                        const float* __restrict__ wk, const float* __restrict__ wv,
                        const float* __restrict__ wo, __half* __restrict__ xh,
                        __half* __restrict__ wqkvh, __half* __restrict__ woh) {
    size_t i = (size_t)(blockIdx.x * blockDim.x + threadIdx.x) * 8;
    if (i >= CVT_TOTAL) return;
    const float* src;
    __half* dst;
    size_t off;
    if (i < SEG0) { src = x; dst = xh; off = i; }
    else if (i < SEG0 + SEG1) { src = wq; dst = wqkvh; off = i - SEG0; }
    else if (i < SEG0 + SEG1 + SEG2) {
        src = wk; dst = wqkvh + SEG1; off = i - SEG0 - SEG1;
    } else if (i < SEG0 + SEG1 + SEG2 + SEG3) {
        src = wv; dst = wqkvh + SEG1 + SEG2; off = i - SEG0 - SEG1 - SEG2;
    } else { src = wo; dst = woh; off = i - SEG0 - SEG1 - SEG2 - SEG3; }

    float4 v0 = *(const float4*)(src + off);
    float4 v1 = *(const float4*)(src + off + 4);
    __half2 h0 = __floats2half2_rn(v0.x, v0.y);
    __half2 h1 = __floats2half2_rn(v0.z, v0.w);
    __half2 h2 = __floats2half2_rn(v1.x, v1.y);
    __half2 h3 = __floats2half2_rn(v1.z, v1.w);
    uint4 o;
    o.x = *(uint32_t*)&h0; o.y = *(uint32_t*)&h1;
    o.z = *(uint32_t*)&h2; o.w = *(uint32_t*)&h3;
    *(uint4*)(dst + off) = o;
}

// ---------------------------------------------------------------------------
// fp16 GEMM: C[M,N] = A[M,K] @ B[N,K]^T + bias
// CTA tile 64x128x64, 128 threads (4 warps, 2x2), warp tile 32x64,
// acc 64 regs/thread -> ~150 regs -> 3 CTAs/SM = 12 warps (3/SMSP):
// enough independent MMA chains to cover LDSM + acc-RAW latency.
// 2-stage cp.async, stride-72 smem, 55.3KB/CTA.
// MODE 0: fp32 out. MODE 1: fused QKV -> split fp16 + RoPE, bias bq/bk/bv.
// ---------------------------------------------------------------------------
#define BK 64
#define GSTR 72
#define A_STG (64 * GSTR)
#define B_STG (128 * GSTR)
#define GEMM_SMEM (2 * (A_STG + B_STG) * 2)   // 55296 bytes

template <int MODE>
__global__ __launch_bounds__(128, 3)
void h_gemm3(const __half* __restrict__ A, const __half* __restrict__ B,
             const float* __restrict__ bias_q, const float* __restrict__ bias_k,
             const float* __restrict__ bias_v, float* __restrict__ Cf,
             __half* __restrict__ Cq, __half* __restrict__ Ck,
             __half* __restrict__ Cv, const float* __restrict__ cs,
             const float* __restrict__ sn, int M, int N, int K) {
    extern __shared__ __half sh[];
    __half* As = sh;                 // [2][64*GSTR]
    __half* Bs = sh + 2 * A_STG;     // [2][128*GSTR]

    const int tid = threadIdx.x;
    const int lane = tid & 31;
    const int wid = tid >> 5;
    const int wm = wid >> 1;   // 0..1  (32 rows each)
    const int wn = wid & 1;    // 0..1  (64 cols each)
    const int bm = blockIdx.y * 64;
    const int bn = blockIdx.x * 128;
    const int lr = lane & 7;
    const int gq = lane >> 3;

    float acc[2][8][4];
#pragma unroll
    for (int mi = 0; mi < 2; mi++)
#pragma unroll
        for (int ni = 0; ni < 8; ni++)
#pragma unroll
            for (int j = 0; j < 4; j++) acc[mi][ni][j] = 0.f;

    auto g2s = [&](int k0, int stg) {
        // A: 64 rows x 8 chunks = 512 -> 4/thread
#pragma unroll
        for (int p = 0; p < 4; p++) {
            int cid = tid + 128 * p;
            int row = cid >> 3;
            int ch = cid & 7;
            cp16(smem_u32(&As[stg * A_STG + row * GSTR + ch * 8]),
                 A + (size_t)(bm + row) * K + k0 + ch * 8);
        }
        // B: 128 rows x 8 chunks = 1024 -> 8/thread
#pragma unroll
        for (int p = 0; p < 8; p++) {
            int cid = tid + 128 * p;
            int row = cid >> 3;
            int ch = cid & 7;
            cp16(smem_u32(&Bs[stg * B_STG + row * GSTR + ch * 8]),
                 B + (size_t)(bn + row) * K + k0 + ch * 8);
        }
    };

    const int nit = K / BK;
    g2s(0, 0); CP_COMMIT;

    for (int it = 0; it < nit; it++) {
        const int buf = it & 1;
        CP_WAIT0;
        __syncthreads();
        if (it + 1 < nit) { g2s((it + 1) * BK, buf ^ 1); CP_COMMIT; }

#pragma unroll
        for (int kk2 = 0; kk2 < 4; kk2++) {
            int kk = kk2 * 16;
            uint32_t a[2][4];
#pragma unroll
            for (int mi = 0; mi < 2; mi++)
                ldsm4(a[mi][0], a[mi][1], a[mi][2], a[mi][3],
                      smem_u32(&As[buf * A_STG +
                                   (wm * 32 + mi * 16 + lr + (gq & 1) * 8) * GSTR +
                                   kk + (gq >> 1) * 8]));
#pragma unroll
            for (int nt = 0; nt < 4; nt++) {
                uint32_t b0, b1, b2, b3;
                ldsm4(b0, b1, b2, b3,
                      smem_u32(&Bs[buf * B_STG +
                                   (wn * 64 + nt * 16 + lr + (gq & 1) * 8) * GSTR +
                                   kk + (gq >> 1) * 8]));
#pragma unroll
                for (int mi = 0; mi < 2; mi++) {
                    mma_f16(acc[mi][nt * 2], a[mi], b0, b2);
                    mma_f16(acc[mi][nt * 2 + 1], a[mi], b1, b3);
                }
            }
        }
    }

    // ---- epilogue ----
    const int r0 = bm + wm * 32 + (lane >> 2);
    const int c0 = bn + wn * 64 + (lane & 3) * 2;
#pragma unroll
    for (int mi = 0; mi < 2; mi++) {
#pragma unroll
        for (int ni = 0; ni < 8; ni++) {
            int r = r0 + mi * 16;
            int c = c0 + ni * 8;
            float2 bb;
            if (MODE == 0) bb = *(const float2*)&bias_q[c];
            else {
                if (c < DIM)                bb = *(const float2*)&bias_q[c];
                else if (c < DIM + KVDIM)   bb = *(const float2*)&bias_k[c - DIM];
                else                        bb = *(const float2*)&bias_v[c - DIM - KVDIM];
            }
            float v00 = acc[mi][ni][0] + bb.x, v01 = acc[mi][ni][1] + bb.y;
            float v10 = acc[mi][ni][2] + bb.x, v11 = acc[mi][ni][3] + bb.y;
            if (MODE == 0) {
                *(float2*)&Cf[(size_t)r * N + c] = make_float2(v00, v01);
                *(float2*)&Cf[(size_t)(r + 8) * N + c] = make_float2(v10, v11);
            } else {
                if (c < DIM + KVDIM) {
                    int i = (c & 127) >> 1;
                    int s0 = r & (SEQ - 1), s1 = (r + 8) & (SEQ - 1);
                    float c00 = cs[s0 * 64 + i], sn0 = sn[s0 * 64 + i];
                    float c10 = cs[s1 * 64 + i], sn1 = sn[s1 * 64 + i];
                    float a0 = v00, b0v = v01;
                    v00 = a0 * c00 - b0v * sn0;
                    v01 = a0 * sn0 + b0v * c00;
                    float a1 = v10, b1v = v11;
                    v10 = a1 * c10 - b1v * sn1;
                    v11 = a1 * sn1 + b1v * c10;
                }
                __half2 h0 = __floats2half2_rn(v00, v01);
                __half2 h1 = __floats2half2_rn(v10, v11);
                __half* dst;
                size_t str;
                int cc;
                if (c < DIM) { dst = Cq; str = DIM; cc = c; }
                else if (c < DIM + KVDIM) { dst = Ck; str = KVDIM; cc = c - DIM; }
                else { dst = Cv; str = KVDIM; cc = c - DIM - KVDIM; }
                *(__half2*)&dst[(size_t)r * str + cc] = h0;
                *(__half2*)&dst[(size_t)(r + 8) * str + cc] = h1;
            }
        }
    }
}

// ---------------------------------------------------------------------------
// Causal GQA flash attention (R10 config, measured 274us) — unchanged.
// QT=64, KT=64, 128 threads, K/V double-buffered, 87KB -> 2 CTAs/SM.
// ---------------------------------------------------------------------------
#define FSTR 136
#define QT 64
#define KT 64
#define FA_SMEM ((QT * FSTR + 2 * KT * FSTR + 2 * KT * FSTR) * 2)  // 87040

__global__ __launch_bounds__(128, 2)
void flash_h(const __half* __restrict__ Q, const __half* __restrict__ K,
             const __half* __restrict__ V, __half* __restrict__ O) {
    extern __shared__ __half sm[];
    __half* Qs = sm;
    __half* Ks = Qs + QT * FSTR;
    __half* Vs = Ks + 2 * KT * FSTR;

    const int tid = threadIdx.x;
    const int lane = tid & 31;
    const int w = tid >> 5;
    const int q0 = (gridDim.x - 1 - blockIdx.x) * QT;
    const int bh = blockIdx.y;
    const int b = bh >> 5;
    const int h = bh & 31;
    const int g = h >> 2;
    const int lr = lane & 7;
    const int gq = lane >> 3;
    const int qr = lane >> 2;
    const int qc = (lane & 3) * 2;

    const __half* Qg = Q + (size_t)(b * SEQ + q0) * DIM + h * HD;
    const __half* Kg = K + (size_t)(b * SEQ) * KVDIM + g * HD;
    const __half* Vg = V + (size_t)(b * SEQ) * KVDIM + g * HD;

#pragma unroll
    for (int p = 0; p < 8; p++) {
        int cid = tid + 128 * p;
        int row = cid >> 4, ch = cid & 15;
        cp16(smem_u32(&Qs[row * FSTR + ch * 8]), Qg + (size_t)row * DIM + ch * 8);
    }
    CP_COMMIT;

    auto ldKV = [&](int kv0, int bufl) {
#pragma unroll
        for (int p = 0; p < 8; p++) {
            int cid = tid + 128 * p;
            int row = cid >> 4, ch = cid & 15;
            cp16(smem_u32(&Ks[bufl * KT * FSTR + row * FSTR + ch * 8]),
                 Kg + (size_t)(kv0 + row) * KVDIM + ch * 8);
            cp16(smem_u32(&Vs[bufl * KT * FSTR + row * FSTR + ch * 8]),
                 Vg + (size_t)(kv0 + row) * KVDIM + ch * 8);
        }
    };
    ldKV(0, 0);
    CP_COMMIT;

    float o[16][4];
#pragma unroll
    for (int nt = 0; nt < 16; nt++)
#pragma unroll
        for (int j = 0; j < 4; j++) o[nt][j] = 0.f;
    float mA = -1e30f, mB = -1e30f, lA = 0.f, lB = 0.f;
    const float scale2 = 0.08838834764831845f * 1.4426950408889634f;
    const int niter = q0 / KT + 1;
    const int rA = q0 + w * 16 + qr;

    for (int it = 0; it < niter; it++) {
        const int kv0 = it * KT;
        const int buf = it & 1;
        CP_WAIT0;
        __syncthreads();
        if (it + 1 < niter) { ldKV((it + 1) * KT, buf ^ 1); CP_COMMIT; }

        float s[8][4];
#pragma unroll
        for (int nt = 0; nt < 8; nt++)
#pragma unroll
            for (int j = 0; j < 4; j++) s[nt][j] = 0.f;

#pragma unroll
        for (int ks = 0; ks < 8; ks++) {
            uint32_t a[4];
            ldsm4(a[0], a[1], a[2], a[3],
                  smem_u32(&Qs[(w * 16 + lr + (gq & 1) * 8) * FSTR +
                               ks * 16 + (gq >> 1) * 8]));
#pragma unroll
            for (int np = 0; np < 4; np++) {
                uint32_t b0, b1, b2, b3;
                ldsm4(b0, b1, b2, b3,
                      smem_u32(&Ks[buf * KT * FSTR +
                                   (np * 16 + lr + (gq & 1) * 8) * FSTR +
                                   ks * 16 + (gq >> 1) * 8]));
                mma_f16(s[np * 2], a, b0, b2);
                mma_f16(s[np * 2 + 1], a, b1, b3);
            }
        }

        const bool domask = (kv0 + KT - 1) > (q0 + w * 16);
#pragma unroll
        for (int nt = 0; nt < 8; nt++)
#pragma unroll
            for (int j = 0; j < 4; j++) {
                float v = s[nt][j] * scale2;
                if (domask) {
                    int col = kv0 + nt * 8 + qc + (j & 1);
                    int row = rA + (j >> 1) * 8;
                    if (col > row) v = -1e30f;
                }
                s[nt][j] = v;
            }

        float rmA = -1e30f, rmB = -1e30f;
#pragma unroll
        for (int nt = 0; nt < 8; nt++) {
            rmA = fmaxf(rmA, fmaxf(s[nt][0], s[nt][1]));
            rmB = fmaxf(rmB, fmaxf(s[nt][2], s[nt][3]));
        }
        rmA = fmaxf(rmA, __shfl_xor_sync(0xffffffffu, rmA, 1));
        rmA = fmaxf(rmA, __shfl_xor_sync(0xffffffffu, rmA, 2));
        rmB = fmaxf(rmB, __shfl_xor_sync(0xffffffffu, rmB, 1));
        rmB = fmaxf(rmB, __shfl_xor_sync(0xffffffffu, rmB, 2));

        float newmA = fmaxf(mA, rmA), newmB = fmaxf(mB, rmB);
        float aAl = fex2(mA - newmA), aBl = fex2(mB - newmB);
        float lsA = 0.f, lsB = 0.f;
#pragma unroll
        for (int nt = 0; nt < 8; nt++) {
            s[nt][0] = fex2(s[nt][0] - newmA);
            s[nt][1] = fex2(s[nt][1] - newmA);
            s[nt][2] = fex2(s[nt][2] - newmB);
            s[nt][3] = fex2(s[nt][3] - newmB);
            lsA += s[nt][0] + s[nt][1];
            lsB += s[nt][2] + s[nt][3];
        }
        lsA += __shfl_xor_sync(0xffffffffu, lsA, 1);
        lsA += __shfl_xor_sync(0xffffffffu, lsA, 2);
        lsB += __shfl_xor_sync(0xffffffffu, lsB, 1);
        lsB += __shfl_xor_sync(0xffffffffu, lsB, 2);
        lA = lA * aAl + lsA;
        lB = lB * aBl + lsB;
        mA = newmA;
        mB = newmB;
        if (!__all_sync(0xffffffffu, (aAl == 1.f) & (aBl == 1.f))) {
#pragma unroll
            for (int nt = 0; nt < 16; nt++) {
                o[nt][0] *= aAl; o[nt][1] *= aAl;
                o[nt][2] *= aBl; o[nt][3] *= aBl;
            }
        }

        uint32_t pa[4][4];
#pragma unroll
        for (int t = 0; t < 4; t++) {
            pa[t][0] = pack_h2(s[2 * t][0], s[2 * t][1]);
            pa[t][1] = pack_h2(s[2 * t][2], s[2 * t][3]);
            pa[t][2] = pack_h2(s[2 * t + 1][0], s[2 * t + 1][1]);
            pa[t][3] = pack_h2(s[2 * t + 1][2], s[2 * t + 1][3]);
        }

#pragma unroll
        for (int t = 0; t < 4; t++) {
#pragma unroll
            for (int np = 0; np < 8; np++) {
                uint32_t v0, v1, v2, v3;
                ldsm4t(v0, v1, v2, v3,
                       smem_u32(&Vs[buf * KT * FSTR +
                                    (t * 16 + lr + (gq & 1) * 8) * FSTR +
                                    np * 16 + (gq >> 1) * 8]));
                mma_f16(o[np * 2], pa[t], v0, v1);
                mma_f16(o[np * 2 + 1], pa[t], v2, v3);
            }
        }
    }

    float iA = 1.f / lA, iB = 1.f / lB;
    __half* Og = O + (size_t)(b * SEQ + q0 + w * 16) * DIM + h * HD;
#pragma unroll
    for (int nt = 0; nt < 16; nt++) {
        int c = nt * 8 + qc;
        *(__half2*)&Og[(size_t)qr * DIM + c] =
            __floats2half2_rn(o[nt][0] * iA, o[nt][1] * iA);
        *(__half2*)&Og[(size_t)(qr + 8) * DIM + c] =
            __floats2half2_rn(o[nt][2] * iB, o[nt][3] * iB);
    }
}

// ---------------------------------------------------------------------------
extern "C" void kernel_launch(void* const* d_in, const int* in_sizes, int n_in,
                              void* d_out, int out_size) {
    const float* x   = (const float*)d_in[0];
    const float* fcs = (const float*)d_in[1];
    const float* fsn = (const float*)d_in[2];
    const float* wq = (const float*)d_in[4];
    const float* bq = (const float*)d_in[5];
    const float* wk = (const float*)d_in[6];
    const float* bk = (const float*)d_in[7];
    const float* wv = (const float*)d_in[8];
    const float* bv = (const float*)d_in[9];
    const float* wo = (const float*)d_in[10];
    const float* bo = (const float*)d_in[11];
    float* out = (float*)d_out;

    __half *xh, *wqkvh, *woh, *qh, *kh, *vh, *ah;
    cudaGetSymbolAddress((void**)&xh, g_xh);
    cudaGetSymbolAddress((void**)&wqkvh, g_wqkvh);
    cudaGetSymbolAddress((void**)&woh, g_woh);
    cudaGetSymbolAddress((void**)&qh, g_qh);
    cudaGetSymbolAddress((void**)&kh, g_kh);
    cudaGetSymbolAddress((void**)&vh, g_vh);
    cudaGetSymbolAddress((void**)&ah, g_ah);

    cudaFuncSetAttribute(h_gemm3<0>, cudaFuncAttributeMaxDynamicSharedMemorySize,
                         GEMM_SMEM);
    cudaFuncSetAttribute(h_gemm3<1>, cudaFuncAttributeMaxDynamicSharedMemorySize,
                         GEMM_SMEM);
    cudaFuncSetAttribute(flash_h, cudaFuncAttributeMaxDynamicSharedMemorySize,
                         FA_SMEM);

    // All fp32->fp16 conversions in ONE launch
    cvt_all<<<(int)((CVT_TOTAL / 8 + 255) / 256), 256>>>(
        x, wq, wk, wv, wo, xh, wqkvh, woh);

    // Fused QKV projection + RoPE epilogue (64x128 CTA tiles, 3 CTAs/SM)
    h_gemm3<1><<<dim3(NQKV / 128, TOK / 64), 128, GEMM_SMEM>>>(
        xh, wqkvh, bq, bk, bv, nullptr, qh, kh, vh, fcs, fsn, TOK, NQKV, DIM);

    // Flash attention
    flash_h<<<dim3(SEQ / QT, BSZ * NHEADS), 128, FA_SMEM>>>(qh, kh, vh, ah);

    // Output projection (fp32 out)
    h_gemm3<0><<<dim3(DIM / 128, TOK / 64), 128, GEMM_SMEM>>>(
        ah, woh, bo, nullptr, nullptr, out, nullptr, nullptr, nullptr,
        nullptr, nullptr, TOK, DIM, DIM);
}